// round 13
// baseline (speedup 1.0000x reference)
#include <cuda_runtime.h>
#include <cuda_fp16.h>
#include <math.h>
#include <stdint.h>

#define BATCH 8192
#define FEAT  2048
#define KROWS 4096           // 2 * FEAT
#define KCH   64             // f16 K elements per stage (128 B/row)
#define NITER (BATCH / KCH)  // 128
#define NSTAGE 3
#define STAGE_BYTES 32768    // A(16KB) + B(16KB) per stage
#define GEMM_SMEM (NSTAGE * STAGE_BYTES + 1024)
#define NTILES 528           // upper-triangular tile count

// ---------------- device scratch ----------------
__device__ __half g_fnh[(size_t)KROWS * BATCH]; // 64 MB normalized rows, f16
__device__ float g_norm2[KROWS];
__device__ float g_S[KROWS];       // sum_{j!=k} exp(sim_kj)
__device__ float g_posraw[FEAT];   // sum_b f1[b,j] * f2[b,j]  (fp32, exact)
__device__ float g_ent;

// ---------------- helpers ----------------
__device__ __forceinline__ uint32_t smem_u32(const void* p) {
    uint32_t a;
    asm("{ .reg .u64 t; cvta.to.shared.u64 t, %1; cvt.u32.u64 %0, t; }" : "=r"(a) : "l"(p));
    return a;
}
__device__ __forceinline__ void cp_async16(uint32_t saddr, const void* gaddr) {
    asm volatile("cp.async.cg.shared.global [%0], [%1], 16;" :: "r"(saddr), "l"(gaddr));
}
__device__ __forceinline__ void ldm_x4(uint32_t& r0, uint32_t& r1, uint32_t& r2, uint32_t& r3,
                                       uint32_t addr) {
    asm volatile("ldmatrix.sync.aligned.m8n8.x4.shared.b16 {%0,%1,%2,%3}, [%4];"
                 : "=r"(r0), "=r"(r1), "=r"(r2), "=r"(r3) : "r"(addr));
}
__device__ __forceinline__ void mma_f32acc(float* c, uint32_t a0, uint32_t a1, uint32_t a2,
                                           uint32_t a3, uint32_t b0, uint32_t b1) {
    asm volatile("mma.sync.aligned.m16n8k16.row.col.f32.f16.f16.f32 "
                 "{%0,%1,%2,%3}, {%4,%5,%6,%7}, {%8,%9}, {%0,%1,%2,%3};"
                 : "+f"(c[0]), "+f"(c[1]), "+f"(c[2]), "+f"(c[3])
                 : "r"(a0), "r"(a1), "r"(a2), "r"(a3), "r"(b0), "r"(b1));
}

// ---------------- kernel 0: zero accumulators ----------------
__global__ void zero_kernel() {
    int i = blockIdx.x * 256 + threadIdx.x;
    if (i < KROWS) { g_S[i] = 0.f; g_norm2[i] = 0.f; }
    if (i < FEAT) g_posraw[i] = 0.f;
    if (i == 0) g_ent = 0.f;
}

// ---------------- kernel 1: fused norms + entropy + pos-dots (512 CTAs) ------------
__global__ void norment_kernel(const float* __restrict__ f1, const float* __restrict__ f2) {
    int col = blockIdx.x * 256 + threadIdx.x;   // 0..2047
    int r0 = blockIdx.y * 128;
    float sq1 = 0.f, sq2 = 0.f, ent = 0.f, pos = 0.f;
    #pragma unroll 4
    for (int r = r0; r < r0 + 128; r++) {
        float v1 = f1[(size_t)r * FEAT + col];
        float v2 = f2[(size_t)r * FEAT + col];
        sq1 += v1 * v1; sq2 += v2 * v2; pos += v1 * v2;
        ent += -v1 * __logf(v1 + 1e-12f) - (1.f - v1) * __logf(1.f - v1 + 1e-12f)
             - v2 * __logf(v2 + 1e-12f) - (1.f - v2) * __logf(1.f - v2 + 1e-12f);
    }
    atomicAdd(&g_norm2[col], sq1);
    atomicAdd(&g_norm2[col + FEAT], sq2);
    atomicAdd(&g_posraw[col], pos);
    __shared__ float sh[256];
    sh[threadIdx.x] = ent;
    __syncthreads();
    for (int s = 128; s > 0; s >>= 1) {
        if (threadIdx.x < s) sh[threadIdx.x] += sh[threadIdx.x + s];
        __syncthreads();
    }
    if (threadIdx.x == 0) atomicAdd(&g_ent, sh[0]);
}

// ---------------- kernel 2: normalize + transpose + f16 convert --------------------
// CTA handles 32 k-rows x 128 batch. float4 loads, 32B uint4 stores.
__global__ void __launch_bounds__(256) transpose_kernel(const float* __restrict__ f1,
                                                        const float* __restrict__ f2) {
    __shared__ float tile[32][129];   // [local k][local b]; 129 = conflict-free pad
    int k0 = blockIdx.x * 32;
    int b0 = blockIdx.y * 128;
    const float* src = (k0 < FEAT) ? f1 : f2;
    int kk0 = (k0 < FEAT) ? k0 : k0 - FEAT;
    int tid = threadIdx.x;

    #pragma unroll
    for (int j = 0; j < 4; j++) {
        int idx = tid + 256 * j;          // 0..1023
        int r  = idx >> 3;                // local batch row 0..127
        int c4 = idx & 7;                 // float4 group 0..7 (covers 32 cols)
        float4 v = *reinterpret_cast<const float4*>(
            &src[(size_t)(b0 + r) * FEAT + kk0 + c4 * 4]);
        tile[c4 * 4 + 0][r] = v.x;
        tile[c4 * 4 + 1][r] = v.y;
        tile[c4 * 4 + 2][r] = v.z;
        tile[c4 * 4 + 3][r] = v.w;
    }
    __syncthreads();

    int kl  = tid >> 3;                   // 0..31
    int b16 = (tid & 7) * 16;             // 0..112
    int k = k0 + kl;
    float rn = rsqrtf(g_norm2[k]);
    uint32_t u[8];
    #pragma unroll
    for (int i = 0; i < 8; i++) {
        __half2 h = __floats2half2_rn(tile[kl][b16 + 2 * i] * rn,
                                      tile[kl][b16 + 2 * i + 1] * rn);
        u[i] = *reinterpret_cast<uint32_t*>(&h);
    }
    __half* dst = &g_fnh[(size_t)k * BATCH + b0 + b16];
    reinterpret_cast<uint4*>(dst)[0] = make_uint4(u[0], u[1], u[2], u[3]);
    reinterpret_cast<uint4*>(dst)[1] = make_uint4(u[4], u[5], u[6], u[7]);
}

// ---------------- kernel 3: HMMA Gram GEMM, 3-stage pipeline, 1 tile/CTA ----------
__device__ __forceinline__ void load_stage(uint32_t sb, int tid,
                                           const __half* Ag, const __half* Bg,
                                           int s, int it) {
    #pragma unroll
    for (int j = 0; j < 8; j++) {
        int c = tid + 256 * j;           // 0..2047 (16B segments)
        int opnd = c >> 10;              // 0 = A, 1 = B
        int row  = (c >> 3) & 127;
        int seg  = c & 7;
        const __half* src = opnd ? Bg : Ag;
        const void* g = src + (size_t)row * BATCH + it * KCH + seg * 8;
        uint32_t off = (uint32_t)(row * 128 + seg * 16);
        off ^= (off >> 3) & 0x70u;       // xor swizzle (conflict-free ldmatrix)
        cp_async16(sb + (uint32_t)s * STAGE_BYTES + (uint32_t)opnd * 16384u + off, g);
    }
    asm volatile("cp.async.commit_group;" ::: "memory");
}

__global__ void __launch_bounds__(256) gemm_kernel() {
    extern __shared__ char smem[];
    uint32_t sb = smem_u32(smem);
    int tid = threadIdx.x, wid = tid >> 5, lane = tid & 31;
    int wm = wid >> 2, wn = wid & 3;     // 2(m) x 4(n) warp grid; warp tile 64 x 32

    int b = blockIdx.x, tm = 0, rl = 32;
    while (b >= rl) { b -= rl; rl--; tm++; }
    int tn = tm + b;

    const __half* Ag = g_fnh + (size_t)tm * 128 * BATCH;
    const __half* Bg = g_fnh + (size_t)tn * 128 * BATCH;

    // A fragment addresses: 4 x ldmatrix.x4 per kk (16 rows each)
    uint32_t aBase[4], aX[4];
    #pragma unroll
    for (int mf = 0; mf < 4; mf++) {
        int r = wm * 64 + mf * 16 + (lane & 15);
        aBase[mf] = (uint32_t)(r * 128);
        aX[mf] = (uint32_t)((r & 7) * 16);
    }
    uint32_t khA = (uint32_t)((lane >> 4) * 16);
    // B fragment addresses: 2 x ldmatrix.x4 per kk, each covering two n-fragments
    uint32_t bBase[2], bX[2];
    #pragma unroll
    for (int nfp = 0; nfp < 2; nfp++) {
        int r = wn * 32 + nfp * 16 + (lane & 7) + ((lane >> 4) & 1) * 8;
        bBase[nfp] = (uint32_t)(r * 128);
        bX[nfp] = (uint32_t)((r & 7) * 16);
    }
    uint32_t khB = (uint32_t)(((lane >> 3) & 1) * 16);

    float acc[4][4][4];
    #pragma unroll
    for (int i = 0; i < 4; i++)
        #pragma unroll
        for (int j = 0; j < 4; j++)
            #pragma unroll
            for (int k = 0; k < 4; k++) acc[i][j][k] = 0.f;

    load_stage(sb, tid, Ag, Bg, 0, 0);
    load_stage(sb, tid, Ag, Bg, 1, 1);

    int s = 0;  // stage of iteration it
    for (int it = 0; it < NITER; ++it) {
        if (it < NITER - 1) asm volatile("cp.async.wait_group 1;" ::: "memory");
        else                asm volatile("cp.async.wait_group 0;" ::: "memory");
        __syncthreads();   // stage s visible; all warps done with stage (s+2)%3

        if (it + 2 < NITER) {
            int sn = s + 2; if (sn >= NSTAGE) sn -= NSTAGE;
            load_stage(sb, tid, Ag, Bg, sn, it + 2);
        }

        uint32_t sA = sb + (uint32_t)s * STAGE_BYTES;
        uint32_t sB = sA + 16384u;
        #pragma unroll
        for (int kk = 0; kk < 4; kk++) {
            uint32_t a[4][4], bb[4][2];
            #pragma unroll
            for (int mf = 0; mf < 4; mf++)
                ldm_x4(a[mf][0], a[mf][1], a[mf][2], a[mf][3],
                       sA + aBase[mf] + (((uint32_t)(kk * 32) + khA) ^ aX[mf]));
            #pragma unroll
            for (int nfp = 0; nfp < 2; nfp++)
                ldm_x4(bb[nfp * 2][0], bb[nfp * 2][1], bb[nfp * 2 + 1][0], bb[nfp * 2 + 1][1],
                       sB + bBase[nfp] + (((uint32_t)(kk * 32) + khB) ^ bX[nfp]));
            #pragma unroll
            for (int mf = 0; mf < 4; mf++)
                #pragma unroll
                for (int nf = 0; nf < 4; nf++)
                    mma_f32acc(acc[mf][nf], a[mf][0], a[mf][1], a[mf][2], a[mf][3],
                               bb[nf][0], bb[nf][1]);
        }
        if (++s == NSTAGE) s = 0;
    }

    // ---- epilogue: exp / row+col sums ----
    float* sh_row = (float*)(smem + NSTAGE * STAGE_BYTES);
    float* sh_col = sh_row + 128;
    __syncthreads();
    if (tid < 128) { sh_row[tid] = 0.f; sh_col[tid] = 0.f; }
    __syncthreads();

    float racc[8], cacc[8];
    #pragma unroll
    for (int i = 0; i < 8; i++) { racc[i] = 0.f; cacc[i] = 0.f; }

    bool diag = (tm == tn);
    #pragma unroll
    for (int mf = 0; mf < 4; mf++)
        #pragma unroll
        for (int im = 0; im < 2; im++) {
            int mg = tm * 128 + wm * 64 + mf * 16 + (lane >> 2) + im * 8;
            #pragma unroll
            for (int nf = 0; nf < 4; nf++)
                #pragma unroll
                for (int in = 0; in < 2; in++) {
                    int ng = tn * 128 + wn * 32 + nf * 8 + 2 * (lane & 3) + in;
                    float v = acc[mf][nf][im * 2 + in] * 2.0f;  // / TEMPERATURE
                    if (mg != ng) {
                        float e = __expf(v);
                        racc[mf * 2 + im] += e;
                        cacc[nf * 2 + in] += e;
                    }
                }
        }
    #pragma unroll
    for (int mf = 0; mf < 4; mf++)
        #pragma unroll
        for (int im = 0; im < 2; im++)
            atomicAdd(&sh_row[wm * 64 + mf * 16 + (lane >> 2) + im * 8], racc[mf * 2 + im]);
    if (!diag) {
        #pragma unroll
        for (int nf = 0; nf < 4; nf++)
            #pragma unroll
            for (int in = 0; in < 2; in++)
                atomicAdd(&sh_col[wn * 32 + nf * 8 + 2 * (lane & 3) + in], cacc[nf * 2 + in]);
    }
    __syncthreads();
    if (tid < 128) {
        atomicAdd(&g_S[tm * 128 + tid], sh_row[tid]);
        if (!diag) atomicAdd(&g_S[tn * 128 + tid], sh_col[tid]);
    }
}

// ---------------- kernel 4: final scalar ----------------
__global__ void final_kernel(float* out) {
    __shared__ float sh[512];
    int t = threadIdx.x;
    float accv = 0.f;
    for (int k = t; k < KROWS; k += 512) {
        float pos = 2.0f * g_posraw[k & (FEAT - 1)] *
                    rsqrtf(g_norm2[k]) * rsqrtf(g_norm2[k ^ FEAT]);
        accv += logf(g_S[k]) - pos;
    }
    sh[t] = accv;
    __syncthreads();
    for (int s = 256; s > 0; s >>= 1) {
        if (t < s) sh[t] += sh[t + s];
        __syncthreads();
    }
    if (t == 0) {
        double ce  = (double)sh[0] / (double)KROWS;
        double nel = (double)g_ent / ((double)KROWS * (double)BATCH) / 0.69314718055994530942;
        out[0] = (float)(ce - nel);
    }
}

// ---------------- launch ----------------
extern "C" void kernel_launch(void* const* d_in, const int* in_sizes, int n_in,
                              void* d_out, int out_size) {
    const float* f1 = (const float*)d_in[0];
    const float* f2 = (const float*)d_in[1];
    float* out = (float*)d_out;

    cudaFuncSetAttribute(gemm_kernel, cudaFuncAttributeMaxDynamicSharedMemorySize, GEMM_SMEM);

    zero_kernel<<<16, 256>>>();
    norment_kernel<<<dim3(8, 64), 256>>>(f1, f2);
    transpose_kernel<<<dim3(KROWS / 32, BATCH / 128), 256>>>(f1, f2);
    gemm_kernel<<<NTILES, 256, GEMM_SMEM>>>();
    final_kernel<<<1, 512>>>(out);
}

// round 14
// speedup vs baseline: 1.0023x; 1.0023x over previous
#include <cuda_runtime.h>
#include <cuda_fp16.h>
#include <math.h>
#include <stdint.h>

#define BATCH 8192
#define FEAT  2048
#define KROWS 4096           // 2 * FEAT
#define KCH   64             // f16 K elements per stage (128 B/row)
#define NITER (BATCH / KCH)  // 128
#define NSTAGE 3
#define STAGE_BYTES 32768    // A(16KB) + B(16KB) per stage
#define GEMM_SMEM (NSTAGE * STAGE_BYTES + 1024)
#define NTILES 528           // upper-triangular tile count

// ---------------- device scratch ----------------
__device__ __half g_fnh[(size_t)KROWS * BATCH]; // 64 MB normalized rows, f16
__device__ float g_norm2[KROWS];
__device__ float g_S[KROWS];       // sum_{j!=k} exp(sim_kj)
__device__ float g_posraw[FEAT];   // sum_b f1[b,j] * f2[b,j]  (fp32, exact)
__device__ float g_ent;

// ---------------- helpers ----------------
__device__ __forceinline__ uint32_t smem_u32(const void* p) {
    uint32_t a;
    asm("{ .reg .u64 t; cvta.to.shared.u64 t, %1; cvt.u32.u64 %0, t; }" : "=r"(a) : "l"(p));
    return a;
}
__device__ __forceinline__ void cp_async16(uint32_t saddr, const void* gaddr) {
    asm volatile("cp.async.cg.shared.global [%0], [%1], 16;" :: "r"(saddr), "l"(gaddr));
}
__device__ __forceinline__ void ldm_x4(uint32_t& r0, uint32_t& r1, uint32_t& r2, uint32_t& r3,
                                       uint32_t addr) {
    asm volatile("ldmatrix.sync.aligned.m8n8.x4.shared.b16 {%0,%1,%2,%3}, [%4];"
                 : "=r"(r0), "=r"(r1), "=r"(r2), "=r"(r3) : "r"(addr));
}
__device__ __forceinline__ void mma_f32acc(float* c, uint32_t a0, uint32_t a1, uint32_t a2,
                                           uint32_t a3, uint32_t b0, uint32_t b1) {
    asm volatile("mma.sync.aligned.m16n8k16.row.col.f32.f16.f16.f32 "
                 "{%0,%1,%2,%3}, {%4,%5,%6,%7}, {%8,%9}, {%0,%1,%2,%3};"
                 : "+f"(c[0]), "+f"(c[1]), "+f"(c[2]), "+f"(c[3])
                 : "r"(a0), "r"(a1), "r"(a2), "r"(a3), "r"(b0), "r"(b1));
}

// ---------------- kernel 0: zero accumulators ----------------
__global__ void zero_kernel() {
    int i = blockIdx.x * 256 + threadIdx.x;
    if (i < KROWS) { g_S[i] = 0.f; g_norm2[i] = 0.f; }
    if (i < FEAT) g_posraw[i] = 0.f;
    if (i == 0) g_ent = 0.f;
}

// ---------------- kernel 1: fused norms + entropy + pos-dots (512 CTAs) ------------
__global__ void norment_kernel(const float* __restrict__ f1, const float* __restrict__ f2) {
    int col = blockIdx.x * 256 + threadIdx.x;   // 0..2047
    int r0 = blockIdx.y * 128;
    float sq1 = 0.f, sq2 = 0.f, ent = 0.f, pos = 0.f;
    #pragma unroll 4
    for (int r = r0; r < r0 + 128; r++) {
        float v1 = f1[(size_t)r * FEAT + col];
        float v2 = f2[(size_t)r * FEAT + col];
        sq1 += v1 * v1; sq2 += v2 * v2; pos += v1 * v2;
        ent += -v1 * __logf(v1 + 1e-12f) - (1.f - v1) * __logf(1.f - v1 + 1e-12f)
             - v2 * __logf(v2 + 1e-12f) - (1.f - v2) * __logf(1.f - v2 + 1e-12f);
    }
    atomicAdd(&g_norm2[col], sq1);
    atomicAdd(&g_norm2[col + FEAT], sq2);
    atomicAdd(&g_posraw[col], pos);
    __shared__ float sh[256];
    sh[threadIdx.x] = ent;
    __syncthreads();
    for (int s = 128; s > 0; s >>= 1) {
        if (threadIdx.x < s) sh[threadIdx.x] += sh[threadIdx.x + s];
        __syncthreads();
    }
    if (threadIdx.x == 0) atomicAdd(&g_ent, sh[0]);
}

// ---------------- kernel 2: normalize + transpose + f16 convert --------------------
// CTA handles 32 k-rows x 128 batch. float4 loads, 32B uint4 stores.
__global__ void __launch_bounds__(256) transpose_kernel(const float* __restrict__ f1,
                                                        const float* __restrict__ f2) {
    __shared__ float tile[32][129];   // [local k][local b]; 129 = conflict-free pad
    int k0 = blockIdx.x * 32;
    int b0 = blockIdx.y * 128;
    const float* src = (k0 < FEAT) ? f1 : f2;
    int kk0 = (k0 < FEAT) ? k0 : k0 - FEAT;
    int tid = threadIdx.x;

    #pragma unroll
    for (int j = 0; j < 4; j++) {
        int idx = tid + 256 * j;          // 0..1023
        int r  = idx >> 3;                // local batch row 0..127
        int c4 = idx & 7;                 // float4 group 0..7 (covers 32 cols)
        float4 v = *reinterpret_cast<const float4*>(
            &src[(size_t)(b0 + r) * FEAT + kk0 + c4 * 4]);
        tile[c4 * 4 + 0][r] = v.x;
        tile[c4 * 4 + 1][r] = v.y;
        tile[c4 * 4 + 2][r] = v.z;
        tile[c4 * 4 + 3][r] = v.w;
    }
    __syncthreads();

    int kl  = tid >> 3;                   // 0..31
    int b16 = (tid & 7) * 16;             // 0..112
    int k = k0 + kl;
    float rn = rsqrtf(g_norm2[k]);
    uint32_t u[8];
    #pragma unroll
    for (int i = 0; i < 8; i++) {
        __half2 h = __floats2half2_rn(tile[kl][b16 + 2 * i] * rn,
                                      tile[kl][b16 + 2 * i + 1] * rn);
        u[i] = *reinterpret_cast<uint32_t*>(&h);
    }
    __half* dst = &g_fnh[(size_t)k * BATCH + b0 + b16];
    reinterpret_cast<uint4*>(dst)[0] = make_uint4(u[0], u[1], u[2], u[3]);
    reinterpret_cast<uint4*>(dst)[1] = make_uint4(u[4], u[5], u[6], u[7]);
}

// ---------------- kernel 3: HMMA Gram GEMM, 3-stage pipeline, 1 tile/CTA ----------
__device__ __forceinline__ void load_stage(uint32_t sb, int tid,
                                           const __half* Ag, const __half* Bg,
                                           int s, int it) {
    #pragma unroll
    for (int j = 0; j < 8; j++) {
        int c = tid + 256 * j;           // 0..2047 (16B segments)
        int opnd = c >> 10;              // 0 = A, 1 = B
        int row  = (c >> 3) & 127;
        int seg  = c & 7;
        const __half* src = opnd ? Bg : Ag;
        const void* g = src + (size_t)row * BATCH + it * KCH + seg * 8;
        uint32_t off = (uint32_t)(row * 128 + seg * 16);
        off ^= (off >> 3) & 0x70u;       // xor swizzle (conflict-free ldmatrix)
        cp_async16(sb + (uint32_t)s * STAGE_BYTES + (uint32_t)opnd * 16384u + off, g);
    }
    asm volatile("cp.async.commit_group;" ::: "memory");
}

__global__ void __launch_bounds__(256) gemm_kernel() {
    extern __shared__ char smem[];
    uint32_t sb = smem_u32(smem);
    int tid = threadIdx.x, wid = tid >> 5, lane = tid & 31;
    int wm = wid >> 2, wn = wid & 3;     // 2(m) x 4(n) warp grid; warp tile 64 x 32

    int b = blockIdx.x, tm = 0, rl = 32;
    while (b >= rl) { b -= rl; rl--; tm++; }
    int tn = tm + b;

    const __half* Ag = g_fnh + (size_t)tm * 128 * BATCH;
    const __half* Bg = g_fnh + (size_t)tn * 128 * BATCH;

    // A fragment addresses: 4 x ldmatrix.x4 per kk (16 rows each)
    uint32_t aBase[4], aX[4];
    #pragma unroll
    for (int mf = 0; mf < 4; mf++) {
        int r = wm * 64 + mf * 16 + (lane & 15);
        aBase[mf] = (uint32_t)(r * 128);
        aX[mf] = (uint32_t)((r & 7) * 16);
    }
    uint32_t khA = (uint32_t)((lane >> 4) * 16);
    // B fragment addresses: 2 x ldmatrix.x4 per kk, each covering two n-fragments
    uint32_t bBase[2], bX[2];
    #pragma unroll
    for (int nfp = 0; nfp < 2; nfp++) {
        int r = wn * 32 + nfp * 16 + (lane & 7) + ((lane >> 4) & 1) * 8;
        bBase[nfp] = (uint32_t)(r * 128);
        bX[nfp] = (uint32_t)((r & 7) * 16);
    }
    uint32_t khB = (uint32_t)(((lane >> 3) & 1) * 16);

    float acc[4][4][4];
    #pragma unroll
    for (int i = 0; i < 4; i++)
        #pragma unroll
        for (int j = 0; j < 4; j++)
            #pragma unroll
            for (int k = 0; k < 4; k++) acc[i][j][k] = 0.f;

    load_stage(sb, tid, Ag, Bg, 0, 0);
    load_stage(sb, tid, Ag, Bg, 1, 1);

    int s = 0;  // stage of iteration it
    for (int it = 0; it < NITER; ++it) {
        if (it < NITER - 1) asm volatile("cp.async.wait_group 1;" ::: "memory");
        else                asm volatile("cp.async.wait_group 0;" ::: "memory");
        __syncthreads();   // stage s visible; all warps done with stage (s+2)%3

        if (it + 2 < NITER) {
            int sn = s + 2; if (sn >= NSTAGE) sn -= NSTAGE;
            load_stage(sb, tid, Ag, Bg, sn, it + 2);
        }

        uint32_t sA = sb + (uint32_t)s * STAGE_BYTES;
        uint32_t sB = sA + 16384u;
        #pragma unroll
        for (int kk = 0; kk < 4; kk++) {
            uint32_t a[4][4], bb[4][2];
            #pragma unroll
            for (int mf = 0; mf < 4; mf++)
                ldm_x4(a[mf][0], a[mf][1], a[mf][2], a[mf][3],
                       sA + aBase[mf] + (((uint32_t)(kk * 32) + khA) ^ aX[mf]));
            #pragma unroll
            for (int nfp = 0; nfp < 2; nfp++)
                ldm_x4(bb[nfp * 2][0], bb[nfp * 2][1], bb[nfp * 2 + 1][0], bb[nfp * 2 + 1][1],
                       sB + bBase[nfp] + (((uint32_t)(kk * 32) + khB) ^ bX[nfp]));
            #pragma unroll
            for (int mf = 0; mf < 4; mf++)
                #pragma unroll
                for (int nf = 0; nf < 4; nf++)
                    mma_f32acc(acc[mf][nf], a[mf][0], a[mf][1], a[mf][2], a[mf][3],
                               bb[nf][0], bb[nf][1]);
        }
        if (++s == NSTAGE) s = 0;
    }

    // ---- epilogue: exp / row+col sums ----
    float* sh_row = (float*)(smem + NSTAGE * STAGE_BYTES);
    float* sh_col = sh_row + 128;
    __syncthreads();
    if (tid < 128) { sh_row[tid] = 0.f; sh_col[tid] = 0.f; }
    __syncthreads();

    float racc[8], cacc[8];
    #pragma unroll
    for (int i = 0; i < 8; i++) { racc[i] = 0.f; cacc[i] = 0.f; }

    bool diag = (tm == tn);
    #pragma unroll
    for (int mf = 0; mf < 4; mf++)
        #pragma unroll
        for (int im = 0; im < 2; im++) {
            int mg = tm * 128 + wm * 64 + mf * 16 + (lane >> 2) + im * 8;
            #pragma unroll
            for (int nf = 0; nf < 4; nf++)
                #pragma unroll
                for (int in = 0; in < 2; in++) {
                    int ng = tn * 128 + wn * 32 + nf * 8 + 2 * (lane & 3) + in;
                    float v = acc[mf][nf][im * 2 + in] * 2.0f;  // / TEMPERATURE
                    if (mg != ng) {
                        float e = __expf(v);
                        racc[mf * 2 + im] += e;
                        cacc[nf * 2 + in] += e;
                    }
                }
        }
    #pragma unroll
    for (int mf = 0; mf < 4; mf++)
        #pragma unroll
        for (int im = 0; im < 2; im++)
            atomicAdd(&sh_row[wm * 64 + mf * 16 + (lane >> 2) + im * 8], racc[mf * 2 + im]);
    if (!diag) {
        #pragma unroll
        for (int nf = 0; nf < 4; nf++)
            #pragma unroll
            for (int in = 0; in < 2; in++)
                atomicAdd(&sh_col[wn * 32 + nf * 8 + 2 * (lane & 3) + in], cacc[nf * 2 + in]);
    }
    __syncthreads();
    if (tid < 128) {
        atomicAdd(&g_S[tm * 128 + tid], sh_row[tid]);
        if (!diag) atomicAdd(&g_S[tn * 128 + tid], sh_col[tid]);
    }
}

// ---------------- kernel 4: final scalar ----------------
__global__ void final_kernel(float* out) {
    __shared__ float sh[512];
    int t = threadIdx.x;
    float accv = 0.f;
    for (int k = t; k < KROWS; k += 512) {
        float pos = 2.0f * g_posraw[k & (FEAT - 1)] *
                    rsqrtf(g_norm2[k]) * rsqrtf(g_norm2[k ^ FEAT]);
        accv += logf(g_S[k]) - pos;
    }
    sh[t] = accv;
    __syncthreads();
    for (int s = 256; s > 0; s >>= 1) {
        if (t < s) sh[t] += sh[t + s];
        __syncthreads();
    }
    if (t == 0) {
        double ce  = (double)sh[0] / (double)KROWS;
        double nel = (double)g_ent / ((double)KROWS * (double)BATCH) / 0.69314718055994530942;
        out[0] = (float)(ce - nel);
    }
}

// ---------------- launch ----------------
extern "C" void kernel_launch(void* const* d_in, const int* in_sizes, int n_in,
                              void* d_out, int out_size) {
    const float* f1 = (const float*)d_in[0];
    const float* f2 = (const float*)d_in[1];
    float* out = (float*)d_out;

    cudaFuncSetAttribute(gemm_kernel, cudaFuncAttributeMaxDynamicSharedMemorySize, GEMM_SMEM);

    zero_kernel<<<16, 256>>>();
    norment_kernel<<<dim3(8, 64), 256>>>(f1, f2);
    transpose_kernel<<<dim3(KROWS / 32, BATCH / 128), 256>>>(f1, f2);
    gemm_kernel<<<NTILES, 256, GEMM_SMEM>>>();
    final_kernel<<<1, 512>>>(out);
}

// round 17
// speedup vs baseline: 1.0373x; 1.0350x over previous
#include <cuda_runtime.h>
#include <cuda_fp16.h>
#include <math.h>
#include <stdint.h>

#define BATCH 8192
#define FEAT  2048
#define KROWS 4096           // 2 * FEAT
#define KCH   64             // f16 K elements per stage (128 B/row)
#define NITER (BATCH / KCH)  // 128
#define NSTAGE 3
#define STAGE_BYTES 32768    // A(16KB) + B(16KB) per stage
#define GEMM_SMEM (NSTAGE * STAGE_BYTES + 1024)
#define NTILES 528           // upper-triangular tile count

// ---------------- device scratch ----------------
__device__ __half g_fh[(size_t)KROWS * BATCH];  // 64 MB RAW rows, f16 (unnormalized)
__device__ float g_norm2[KROWS];
__device__ float g_S[KROWS];       // sum_{j!=k} exp(sim_kj)
__device__ float g_posraw[FEAT];   // sum_b f1[b,j] * f2[b,j]  (fp32, exact)
__device__ float g_ent;

// ---------------- helpers ----------------
__device__ __forceinline__ uint32_t smem_u32(const void* p) {
    uint32_t a;
    asm("{ .reg .u64 t; cvta.to.shared.u64 t, %1; cvt.u32.u64 %0, t; }" : "=r"(a) : "l"(p));
    return a;
}
__device__ __forceinline__ void cp_async16(uint32_t saddr, const void* gaddr) {
    asm volatile("cp.async.cg.shared.global [%0], [%1], 16;" :: "r"(saddr), "l"(gaddr));
}
__device__ __forceinline__ void ldm_x4(uint32_t& r0, uint32_t& r1, uint32_t& r2, uint32_t& r3,
                                       uint32_t addr) {
    asm volatile("ldmatrix.sync.aligned.m8n8.x4.shared.b16 {%0,%1,%2,%3}, [%4];"
                 : "=r"(r0), "=r"(r1), "=r"(r2), "=r"(r3) : "r"(addr));
}
__device__ __forceinline__ void mma_f32acc(float* c, uint32_t a0, uint32_t a1, uint32_t a2,
                                           uint32_t a3, uint32_t b0, uint32_t b1) {
    asm volatile("mma.sync.aligned.m16n8k16.row.col.f32.f16.f16.f32 "
                 "{%0,%1,%2,%3}, {%4,%5,%6,%7}, {%8,%9}, {%0,%1,%2,%3};"
                 : "+f"(c[0]), "+f"(c[1]), "+f"(c[2]), "+f"(c[3])
                 : "r"(a0), "r"(a1), "r"(a2), "r"(a3), "r"(b0), "r"(b1));
}

// ---------------- kernel 0: zero accumulators ----------------
__global__ void zero_kernel() {
    int i = blockIdx.x * 256 + threadIdx.x;
    if (i < KROWS) { g_S[i] = 0.f; g_norm2[i] = 0.f; }
    if (i < FEAT) g_posraw[i] = 0.f;
    if (i == 0) g_ent = 0.f;
}

// ---------------- kernel 1: FUSED norms + entropy + pos-dots + transpose + f16 -----
// CTA: 32 feature-cols x 128 batch-rows of BOTH f1 and f2. One read of inputs total.
__global__ void __launch_bounds__(256) prep_kernel(const float* __restrict__ f1,
                                                   const float* __restrict__ f2) {
    __shared__ float t1[32][129];
    __shared__ float t2[32][129];
    __shared__ float s_sq1[32], s_sq2[32], s_pos[32];
    __shared__ float s_ent[256];
    int c0 = blockIdx.x * 32;
    int b0 = blockIdx.y * 128;
    int tid = threadIdx.x;
    if (tid < 32) { s_sq1[tid] = 0.f; s_sq2[tid] = 0.f; s_pos[tid] = 0.f; }

    #pragma unroll
    for (int j = 0; j < 4; j++) {
        int idx = tid + 256 * j;          // 0..1023
        int r  = idx >> 3;                // batch row 0..127
        int c4 = idx & 7;                 // float4 group
        float4 v = *reinterpret_cast<const float4*>(&f1[(size_t)(b0 + r) * FEAT + c0 + c4 * 4]);
        t1[c4 * 4 + 0][r] = v.x; t1[c4 * 4 + 1][r] = v.y;
        t1[c4 * 4 + 2][r] = v.z; t1[c4 * 4 + 3][r] = v.w;
        float4 w = *reinterpret_cast<const float4*>(&f2[(size_t)(b0 + r) * FEAT + c0 + c4 * 4]);
        t2[c4 * 4 + 0][r] = w.x; t2[c4 * 4 + 1][r] = w.y;
        t2[c4 * 4 + 2][r] = w.z; t2[c4 * 4 + 3][r] = w.w;
    }
    __syncthreads();

    // per-column partial sums (8 threads per column, 16 rows each)
    {
        int col = tid & 31, rb = tid >> 5;
        float sq1 = 0.f, sq2 = 0.f, pos = 0.f, ent = 0.f;
        #pragma unroll
        for (int i = 0; i < 16; i++) {
            int r = rb * 16 + i;
            float v1 = t1[col][r], v2 = t2[col][r];
            sq1 += v1 * v1; sq2 += v2 * v2; pos += v1 * v2;
            ent += -v1 * __logf(v1 + 1e-12f) - (1.f - v1) * __logf(1.f - v1 + 1e-12f)
                 - v2 * __logf(v2 + 1e-12f) - (1.f - v2) * __logf(1.f - v2 + 1e-12f);
        }
        atomicAdd(&s_sq1[col], sq1);
        atomicAdd(&s_sq2[col], sq2);
        atomicAdd(&s_pos[col], pos);
        s_ent[tid] = ent;
    }
    __syncthreads();
    for (int s = 128; s > 0; s >>= 1) {
        if (tid < s) s_ent[tid] += s_ent[tid + s];
        __syncthreads();
    }
    if (tid == 0) atomicAdd(&g_ent, s_ent[0]);
    if (tid < 32) {
        atomicAdd(&g_norm2[c0 + tid], s_sq1[tid]);
        atomicAdd(&g_norm2[FEAT + c0 + tid], s_sq2[tid]);
        atomicAdd(&g_posraw[c0 + tid], s_pos[tid]);
    }

    // raw f16 transposed writes (32 B per half per thread)
    int kl  = tid >> 3;                   // 0..31
    int b16 = (tid & 7) * 16;             // 0..112
    uint32_t u[8];
    #pragma unroll
    for (int i = 0; i < 8; i++) {
        __half2 h = __floats2half2_rn(t1[kl][b16 + 2 * i], t1[kl][b16 + 2 * i + 1]);
        u[i] = *reinterpret_cast<uint32_t*>(&h);
    }
    __half* d1 = &g_fh[(size_t)(c0 + kl) * BATCH + b0 + b16];
    reinterpret_cast<uint4*>(d1)[0] = make_uint4(u[0], u[1], u[2], u[3]);
    reinterpret_cast<uint4*>(d1)[1] = make_uint4(u[4], u[5], u[6], u[7]);
    #pragma unroll
    for (int i = 0; i < 8; i++) {
        __half2 h = __floats2half2_rn(t2[kl][b16 + 2 * i], t2[kl][b16 + 2 * i + 1]);
        u[i] = *reinterpret_cast<uint32_t*>(&h);
    }
    __half* d2 = &g_fh[(size_t)(FEAT + c0 + kl) * BATCH + b0 + b16];
    reinterpret_cast<uint4*>(d2)[0] = make_uint4(u[0], u[1], u[2], u[3]);
    reinterpret_cast<uint4*>(d2)[1] = make_uint4(u[4], u[5], u[6], u[7]);
}

// ---------------- kernel 2: HMMA Gram GEMM, 3-stage pipeline, 1 tile/CTA ----------
__device__ __forceinline__ void load_stage(uint32_t sb, int tid,
                                           const __half* Ag, const __half* Bg,
                                           int s, int it) {
    #pragma unroll
    for (int j = 0; j < 8; j++) {
        int c = tid + 256 * j;           // 0..2047 (16B segments)
        int opnd = c >> 10;              // 0 = A, 1 = B
        int row  = (c >> 3) & 127;
        int seg  = c & 7;
        const __half* src = opnd ? Bg : Ag;
        const void* g = src + (size_t)row * BATCH + it * KCH + seg * 8;
        uint32_t off = (uint32_t)(row * 128 + seg * 16);
        off ^= (off >> 3) & 0x70u;       // xor swizzle (conflict-free ldmatrix)
        cp_async16(sb + (uint32_t)s * STAGE_BYTES + (uint32_t)opnd * 16384u + off, g);
    }
    asm volatile("cp.async.commit_group;" ::: "memory");
}

__global__ void __launch_bounds__(256) gemm_kernel() {
    extern __shared__ char smem[];
    uint32_t sb = smem_u32(smem);
    int tid = threadIdx.x, wid = tid >> 5, lane = tid & 31;
    int wm = wid >> 2, wn = wid & 3;     // 2(m) x 4(n) warp grid; warp tile 64 x 32

    int b = blockIdx.x, tm = 0, rl = 32;
    while (b >= rl) { b -= rl; rl--; tm++; }
    int tn = tm + b;

    const __half* Ag = g_fh + (size_t)tm * 128 * BATCH;
    const __half* Bg = g_fh + (size_t)tn * 128 * BATCH;

    uint32_t aBase[4], aX[4];
    #pragma unroll
    for (int mf = 0; mf < 4; mf++) {
        int r = wm * 64 + mf * 16 + (lane & 15);
        aBase[mf] = (uint32_t)(r * 128);
        aX[mf] = (uint32_t)((r & 7) * 16);
    }
    uint32_t khA = (uint32_t)((lane >> 4) * 16);
    uint32_t bBase[2], bX[2];
    #pragma unroll
    for (int nfp = 0; nfp < 2; nfp++) {
        int r = wn * 32 + nfp * 16 + (lane & 7) + ((lane >> 4) & 1) * 8;
        bBase[nfp] = (uint32_t)(r * 128);
        bX[nfp] = (uint32_t)((r & 7) * 16);
    }
    uint32_t khB = (uint32_t)(((lane >> 3) & 1) * 16);

    float acc[4][4][4];
    #pragma unroll
    for (int i = 0; i < 4; i++)
        #pragma unroll
        for (int j = 0; j < 4; j++)
            #pragma unroll
            for (int k = 0; k < 4; k++) acc[i][j][k] = 0.f;

    load_stage(sb, tid, Ag, Bg, 0, 0);
    load_stage(sb, tid, Ag, Bg, 1, 1);

    int s = 0;  // stage of iteration it
    for (int it = 0; it < NITER; ++it) {
        if (it < NITER - 1) asm volatile("cp.async.wait_group 1;" ::: "memory");
        else                asm volatile("cp.async.wait_group 0;" ::: "memory");
        __syncthreads();

        if (it + 2 < NITER) {
            int sn = s + 2; if (sn >= NSTAGE) sn -= NSTAGE;
            load_stage(sb, tid, Ag, Bg, sn, it + 2);
        }

        uint32_t sA = sb + (uint32_t)s * STAGE_BYTES;
        uint32_t sB = sA + 16384u;
        #pragma unroll
        for (int kk = 0; kk < 4; kk++) {
            uint32_t a[4][4], bb[4][2];
            #pragma unroll
            for (int mf = 0; mf < 4; mf++)
                ldm_x4(a[mf][0], a[mf][1], a[mf][2], a[mf][3],
                       sA + aBase[mf] + (((uint32_t)(kk * 32) + khA) ^ aX[mf]));
            #pragma unroll
            for (int nfp = 0; nfp < 2; nfp++)
                ldm_x4(bb[nfp * 2][0], bb[nfp * 2][1], bb[nfp * 2 + 1][0], bb[nfp * 2 + 1][1],
                       sB + bBase[nfp] + (((uint32_t)(kk * 32) + khB) ^ bX[nfp]));
            #pragma unroll
            for (int mf = 0; mf < 4; mf++)
                #pragma unroll
                for (int nf = 0; nf < 4; nf++)
                    mma_f32acc(acc[mf][nf], a[mf][0], a[mf][1], a[mf][2], a[mf][3],
                               bb[nf][0], bb[nf][1]);
        }
        if (++s == NSTAGE) s = 0;
    }

    // ---- epilogue: normalize scales + exp / row+col sums ----
    float* sh_row = (float*)(smem + NSTAGE * STAGE_BYTES);
    float* sh_col = sh_row + 128;
    __syncthreads();
    if (tid < 128) { sh_row[tid] = 0.f; sh_col[tid] = 0.f; }
    __syncthreads();

    float rsm[8], rsn[8];
    #pragma unroll
    for (int mf = 0; mf < 4; mf++)
        #pragma unroll
        for (int im = 0; im < 2; im++)
            rsm[mf * 2 + im] = rsqrtf(g_norm2[tm * 128 + wm * 64 + mf * 16 + (lane >> 2) + im * 8]);
    #pragma unroll
    for (int nf = 0; nf < 4; nf++)
        #pragma unroll
        for (int in = 0; in < 2; in++)
            rsn[nf * 2 + in] = rsqrtf(g_norm2[tn * 128 + wn * 32 + nf * 8 + 2 * (lane & 3) + in]);

    float racc[8], cacc[8];
    #pragma unroll
    for (int i = 0; i < 8; i++) { racc[i] = 0.f; cacc[i] = 0.f; }

    bool diag = (tm == tn);
    #pragma unroll
    for (int mf = 0; mf < 4; mf++)
        #pragma unroll
        for (int im = 0; im < 2; im++) {
            int mg = tm * 128 + wm * 64 + mf * 16 + (lane >> 2) + im * 8;
            #pragma unroll
            for (int nf = 0; nf < 4; nf++)
                #pragma unroll
                for (int in = 0; in < 2; in++) {
                    int ng = tn * 128 + wn * 32 + nf * 8 + 2 * (lane & 3) + in;
                    float v = acc[mf][nf][im * 2 + in] *
                              (2.0f * rsm[mf * 2 + im] * rsn[nf * 2 + in]);
                    if (mg != ng) {
                        float e = __expf(v);
                        racc[mf * 2 + im] += e;
                        cacc[nf * 2 + in] += e;
                    }
                }
        }
    #pragma unroll
    for (int mf = 0; mf < 4; mf++)
        #pragma unroll
        for (int im = 0; im < 2; im++)
            atomicAdd(&sh_row[wm * 64 + mf * 16 + (lane >> 2) + im * 8], racc[mf * 2 + im]);
    if (!diag) {
        #pragma unroll
        for (int nf = 0; nf < 4; nf++)
            #pragma unroll
            for (int in = 0; in < 2; in++)
                atomicAdd(&sh_col[wn * 32 + nf * 8 + 2 * (lane & 3) + in], cacc[nf * 2 + in]);
    }
    __syncthreads();
    if (tid < 128) {
        atomicAdd(&g_S[tm * 128 + tid], sh_row[tid]);
        if (!diag) atomicAdd(&g_S[tn * 128 + tid], sh_col[tid]);
    }
}

// ---------------- kernel 3: final scalar ----------------
__global__ void final_kernel(float* out) {
    __shared__ float sh[512];
    int t = threadIdx.x;
    float accv = 0.f;
    for (int k = t; k < KROWS; k += 512) {
        float pos = 2.0f * g_posraw[k & (FEAT - 1)] *
                    rsqrtf(g_norm2[k]) * rsqrtf(g_norm2[k ^ FEAT]);
        accv += logf(g_S[k]) - pos;
    }
    sh[t] = accv;
    __syncthreads();
    for (int s = 256; s > 0; s >>= 1) {
        if (t < s) sh[t] += sh[t + s];
        __syncthreads();
    }
    if (t == 0) {
        double ce  = (double)sh[0] / (double)KROWS;
        double nel = (double)g_ent / ((double)KROWS * (double)BATCH) / 0.69314718055994530942;
        out[0] = (float)(ce - nel);
    }
}

// ---------------- launch ----------------
extern "C" void kernel_launch(void* const* d_in, const int* in_sizes, int n_in,
                              void* d_out, int out_size) {
    const float* f1 = (const float*)d_in[0];
    const float* f2 = (const float*)d_in[1];
    float* out = (float*)d_out;

    cudaFuncSetAttribute(gemm_kernel, cudaFuncAttributeMaxDynamicSharedMemorySize, GEMM_SMEM);

    zero_kernel<<<16, 256>>>();
    prep_kernel<<<dim3(FEAT / 32, BATCH / 128), 256>>>(f1, f2);
    gemm_kernel<<<NTILES, 256, GEMM_SMEM>>>();
    final_kernel<<<1, 512>>>(out);
}